// round 9
// baseline (speedup 1.0000x reference)
#include <cuda_runtime.h>
#include <math.h>
#include <stdint.h>

#define H 256
#define G3 768
#define FD 128
#define HEADN 128
#define KC 16
#define HS_PITCH 36
#define XP 132            // padded SMEM pitch for mma fragment tiles

typedef unsigned long long ull;

// ---- packed fp32x2 (bit-exact double-rate FFMA) ----
#define FMA2(acc, a, b) \
    asm volatile("fma.rn.f32x2 %0, %1, %2, %0;" : "+l"(acc) : "l"(a), "l"(b))
#define PACK2(out, lo, hi) \
    asm volatile("mov.b64 %0, {%1, %2};" : "=l"(out) : "f"(lo), "f"(hi))
#define UNPACK2(lo, hi, in) \
    asm volatile("mov.b64 {%0, %1}, %2;" : "=f"(lo), "=f"(hi) : "l"(in))

__device__ __forceinline__ void cp16(void* smem_dst, const void* gsrc) {
    unsigned d = (unsigned)__cvta_generic_to_shared(smem_dst);
    asm volatile("cp.async.cg.shared.global [%0], [%1], 16;" :: "r"(d), "l"(gsrc));
}
#define CP_COMMIT asm volatile("cp.async.commit_group;")
#define CP_WAIT1  asm volatile("cp.async.wait_group 1;")
#define CP_WAIT0  asm volatile("cp.async.wait_group 0;")

__device__ __forceinline__ uint32_t f2tf32(float f) {
    uint32_t o;
    asm("cvt.rna.tf32.f32 %0, %1;" : "=r"(o) : "f"(f));
    return o;
}

// mma.sync m16n8k8 tf32 (A row-major, B col-major), acc in-place
#define MMA_TF32(c, a, b) \
    asm volatile("mma.sync.aligned.m16n8k8.row.col.f32.tf32.tf32.f32 " \
        "{%0,%1,%2,%3}, {%4,%5,%6,%7}, {%8,%9}, {%0,%1,%2,%3};" \
        : "+f"((c)[0]), "+f"((c)[1]), "+f"((c)[2]), "+f"((c)[3]) \
        : "r"((a)[0]), "r"((a)[1]), "r"((a)[2]), "r"((a)[3]), \
          "r"((b)[0]), "r"((b)[1]))

// ---------------- scratch ----------------
__device__ float g_xg[4096UL * 64UL * 768UL];
__device__ float g_whhT[H * G3];
__device__ float g_whead[H * HEADN];

// ---------------- kernel 0: pack ----------------
__global__ void pack_weights(const float* __restrict__ w_hh,
                             const float* __restrict__ w_pi,
                             const float* __restrict__ w_vf) {
    int idx = blockIdx.x * blockDim.x + threadIdx.x;
    int stride = gridDim.x * blockDim.x;
    for (int i = idx; i < H * G3; i += stride) {
        int k = i / G3, g = i % G3;
        g_whhT[i] = w_hh[g * H + k];
    }
    for (int i = idx; i < H * HEADN; i += stride) {
        int k = i / HEADN, j = i % HEADN;
        g_whead[i] = (j < 64) ? w_pi[j * H + k] : w_vf[(j - 64) * H + k];
    }
}

// ---------------- kernel 1: x_gates via mma.sync tf32 ----------------
__global__ __launch_bounds__(256, 1) void xgates_mma_sync(const float* __restrict__ feats,
                                                          const float* __restrict__ w_ih,
                                                          const float* __restrict__ b_ih) {
    extern __shared__ uint32_t xs[];
    uint32_t* As = xs;                 // [128][XP]
    uint32_t* Bs = xs + 128 * XP;      // [128][XP]

    const int t = threadIdx.x;
    const int lane = t & 31;
    const int w = t >> 5;
    const int wm = w & 1;
    const int wn = w >> 1;
    const int m0 = blockIdx.x * 128;
    const int n0 = blockIdx.y * 128;

#pragma unroll
    for (int q = 0; q < 16; q++) {
        int idx = t + 256 * q, row = idx >> 5, c4 = idx & 31;
        float4 va = *reinterpret_cast<const float4*>(
            &feats[(size_t)(m0 + row) * FD + c4 * 4]);
        uint4 ua = {f2tf32(va.x), f2tf32(va.y), f2tf32(va.z), f2tf32(va.w)};
        *reinterpret_cast<uint4*>(&As[row * XP + c4 * 4]) = ua;
        float4 vb = *reinterpret_cast<const float4*>(
            &w_ih[(size_t)(n0 + row) * FD + c4 * 4]);
        uint4 ub = {f2tf32(vb.x), f2tf32(vb.y), f2tf32(vb.z), f2tf32(vb.w)};
        *reinterpret_cast<uint4*>(&Bs[row * XP + c4 * 4]) = ub;
    }
    __syncthreads();

    float acc[16][4];
#pragma unroll
    for (int i = 0; i < 16; i++)
#pragma unroll
        for (int j = 0; j < 4; j++) acc[i][j] = 0.f;

    const int rA = wm * 64 + (lane >> 2);
    const int rB = wn * 32 + (lane >> 2);
    const int kl = lane & 3;

#pragma unroll
    for (int ks = 0; ks < 16; ks++) {
        const int k0 = ks * 8 + kl;
        uint32_t a[4][4], b[4][2];
#pragma unroll
        for (int mt = 0; mt < 4; mt++) {
            const int r = rA + mt * 16;
            a[mt][0] = As[r * XP + k0];
            a[mt][1] = As[(r + 8) * XP + k0];
            a[mt][2] = As[r * XP + k0 + 4];
            a[mt][3] = As[(r + 8) * XP + k0 + 4];
        }
#pragma unroll
        for (int nt = 0; nt < 4; nt++) {
            const int n = rB + nt * 8;
            b[nt][0] = Bs[n * XP + k0];
            b[nt][1] = Bs[n * XP + k0 + 4];
        }
#pragma unroll
        for (int mt = 0; mt < 4; mt++)
#pragma unroll
            for (int nt = 0; nt < 4; nt++)
                MMA_TF32(acc[mt * 4 + nt], a[mt], b[nt]);
    }

#pragma unroll
    for (int nt = 0; nt < 4; nt++) {
        const int col = n0 + wn * 32 + nt * 8 + 2 * kl;
        const float bx = b_ih[col], by = b_ih[col + 1];
#pragma unroll
        for (int mt = 0; mt < 4; mt++) {
            const int r = m0 + wm * 64 + mt * 16 + (lane >> 2);
            float2 v0 = {acc[mt * 4 + nt][0] + bx, acc[mt * 4 + nt][1] + by};
            float2 v1 = {acc[mt * 4 + nt][2] + bx, acc[mt * 4 + nt][3] + by};
            *reinterpret_cast<float2*>(&g_xg[(size_t)r * G3 + col]) = v0;
            *reinterpret_cast<float2*>(&g_xg[(size_t)(r + 8) * G3 + col]) = v1;
        }
    }
}

// ---------------- kernel 2: persistent GRU recurrence + heads ----------------
// CTA owns 32 batch rows; h in SMEM. Warp w: wp = w&1 (column half),
// rg = w>>1 (row group: rows rg*8..rg*8+7). Lane tn owns column pairs
// p = q*64 + wp*32 + tn (q=0..5): q0/q1 -> r gate (hidden i0A/i0B),
// q2/q3 -> z, q4/q5 -> n, with i0A = 2*(wp*32+tn), i0B = i0A+128.
// Each weight LDS.64 feeds 8 rows -> SMEM crossbar no longer co-binding.
__global__ __launch_bounds__(256) void gru_recur(const float* __restrict__ b_hh,
                                                 const float* __restrict__ b_pi,
                                                 const float* __restrict__ b_vf,
                                                 float* __restrict__ out,
                                                 int Btot, int Tsteps) {
    extern __shared__ float sm[];
    float* Hs = sm;                       // [256][HS_PITCH]
    float* Ws0 = sm + H * HS_PITCH;       // [2][KC][768]
    float* Ws1 = Ws0 + KC * G3;

    const int t  = threadIdx.x;
    const int tn = t & 31;
    const int w  = t >> 5;
    const int wp = w & 1;
    const int rg = w >> 1;                // 0..3
    const int b0 = blockIdx.x * 32;

    const int i0A = 2 * (wp * 32 + tn);   // even, in [0,128)
    const int i0B = i0A + 128;
    // hoist all gate biases (constant across steps)
    const float2 bhrA = *reinterpret_cast<const float2*>(&b_hh[i0A]);
    const float2 bhrB = *reinterpret_cast<const float2*>(&b_hh[i0B]);
    const float2 bhzA = *reinterpret_cast<const float2*>(&b_hh[H + i0A]);
    const float2 bhzB = *reinterpret_cast<const float2*>(&b_hh[H + i0B]);
    const float2 bhnA = *reinterpret_cast<const float2*>(&b_hh[2 * H + i0A]);
    const float2 bhnB = *reinterpret_cast<const float2*>(&b_hh[2 * H + i0B]);

    for (int i = t; i < H * HS_PITCH; i += 256) Hs[i] = 0.f;
    __syncthreads();

    const int NCH = H / KC;

    for (int st = 0; st < Tsteps; st++) {
#pragma unroll
        for (int q = 0; q < 12; q++) {
            int f4 = t + 256 * q, row = f4 / 192, c4 = f4 % 192;
            cp16(&Ws0[row * G3 + c4 * 4], &g_whhT[(size_t)row * G3 + c4 * 4]);
        }
        CP_COMMIT;

        ull acc[8][6];
#pragma unroll
        for (int i = 0; i < 8; i++)
#pragma unroll
            for (int q = 0; q < 6; q++) acc[i][q] = 0ULL;

        for (int c = 0; c < NCH; c++) {
            float* Wcur = (c & 1) ? Ws1 : Ws0;
            if (c + 1 < NCH) {
                float* Wnxt = ((c + 1) & 1) ? Ws1 : Ws0;
                const int k0n = (c + 1) * KC;
#pragma unroll
                for (int q = 0; q < 12; q++) {
                    int f4 = t + 256 * q, row = f4 / 192, c4 = f4 % 192;
                    cp16(&Wnxt[row * G3 + c4 * 4], &g_whhT[(size_t)(k0n + row) * G3 + c4 * 4]);
                }
                CP_COMMIT;
                CP_WAIT1;
            } else {
                CP_WAIT0;
            }
            __syncthreads();

            const int k0 = c * KC;
#pragma unroll
            for (int kk = 0; kk < KC; kk++) {
                // 8 h-values of this warp's row group (broadcast loads)
                const float4 h0 = *reinterpret_cast<const float4*>(
                    &Hs[(k0 + kk) * HS_PITCH + rg * 8]);
                const float4 h1 = *reinterpret_cast<const float4*>(
                    &Hs[(k0 + kk) * HS_PITCH + rg * 8 + 4]);
                ull a2[8];
                PACK2(a2[0], h0.x, h0.x); PACK2(a2[1], h0.y, h0.y);
                PACK2(a2[2], h0.z, h0.z); PACK2(a2[3], h0.w, h0.w);
                PACK2(a2[4], h1.x, h1.x); PACK2(a2[5], h1.y, h1.y);
                PACK2(a2[6], h1.z, h1.z); PACK2(a2[7], h1.w, h1.w);
                const ull* wrow = reinterpret_cast<const ull*>(Wcur + kk * G3);
                ull wv[6];
#pragma unroll
                for (int q = 0; q < 6; q++)
                    wv[q] = wrow[q * 64 + wp * 32 + tn];    // LDS.64, conflict-free
#pragma unroll
                for (int q = 0; q < 6; q++)
#pragma unroll
                    for (int r = 0; r < 8; r++)
                        FMA2(acc[r][q], a2[r], wv[q]);
            }
            __syncthreads();
        }

        // gate math + h update (thread owns hidden pairs i0A,i0B x 8 rows)
#pragma unroll
        for (int ri = 0; ri < 8; ri++) {
            const int row = rg * 8 + ri;
            const size_t gro = ((size_t)(b0 + row) * Tsteps + st) * G3;
            {   // hidden pair i0A: r=acc[ri][0], z=acc[ri][2], n=acc[ri][4]
                const float2 xr = *reinterpret_cast<const float2*>(&g_xg[gro + i0A]);
                const float2 xz = *reinterpret_cast<const float2*>(&g_xg[gro + H + i0A]);
                const float2 xn = *reinterpret_cast<const float2*>(&g_xg[gro + 2 * H + i0A]);
                float hr0, hr1, hz0, hz1, hn0, hn1;
                UNPACK2(hr0, hr1, acc[ri][0]);
                UNPACK2(hz0, hz1, acc[ri][2]);
                UNPACK2(hn0, hn1, acc[ri][4]);
                {
                    const float r = 1.f / (1.f + __expf(-(xr.x + hr0 + bhrA.x)));
                    const float z = 1.f / (1.f + __expf(-(xz.x + hz0 + bhzA.x)));
                    const float n = tanhf(xn.x + r * (hn0 + bhnA.x));
                    const float hold = Hs[i0A * HS_PITCH + row];
                    Hs[i0A * HS_PITCH + row] = (1.f - z) * n + z * hold;
                }
                {
                    const float r = 1.f / (1.f + __expf(-(xr.y + hr1 + bhrA.y)));
                    const float z = 1.f / (1.f + __expf(-(xz.y + hz1 + bhzA.y)));
                    const float n = tanhf(xn.y + r * (hn1 + bhnA.y));
                    const float hold = Hs[(i0A + 1) * HS_PITCH + row];
                    Hs[(i0A + 1) * HS_PITCH + row] = (1.f - z) * n + z * hold;
                }
            }
            {   // hidden pair i0B: r=acc[ri][1], z=acc[ri][3], n=acc[ri][5]
                const float2 xr = *reinterpret_cast<const float2*>(&g_xg[gro + i0B]);
                const float2 xz = *reinterpret_cast<const float2*>(&g_xg[gro + H + i0B]);
                const float2 xn = *reinterpret_cast<const float2*>(&g_xg[gro + 2 * H + i0B]);
                float hr0, hr1, hz0, hz1, hn0, hn1;
                UNPACK2(hr0, hr1, acc[ri][1]);
                UNPACK2(hz0, hz1, acc[ri][3]);
                UNPACK2(hn0, hn1, acc[ri][5]);
                {
                    const float r = 1.f / (1.f + __expf(-(xr.x + hr0 + bhrB.x)));
                    const float z = 1.f / (1.f + __expf(-(xz.x + hz0 + bhzB.x)));
                    const float n = tanhf(xn.x + r * (hn0 + bhnB.x));
                    const float hold = Hs[i0B * HS_PITCH + row];
                    Hs[i0B * HS_PITCH + row] = (1.f - z) * n + z * hold;
                }
                {
                    const float r = 1.f / (1.f + __expf(-(xr.y + hr1 + bhrB.y)));
                    const float z = 1.f / (1.f + __expf(-(xz.y + hz1 + bhzB.y)));
                    const float n = tanhf(xn.y + r * (hn1 + bhnB.y));
                    const float hold = Hs[(i0B + 1) * HS_PITCH + row];
                    Hs[(i0B + 1) * HS_PITCH + row] = (1.f - z) * n + z * hold;
                }
            }
        }
        __syncthreads();
    }

    // LeakyReLU on final h (full sweep, conflict-free: lanes -> adjacent rows)
    for (int idx = t; idx < H * 32; idx += 256) {
        const int hid = idx >> 5, row = idx & 31;
        float v = Hs[hid * HS_PITCH + row];
        Hs[hid * HS_PITCH + row] = (v >= 0.f) ? v : 0.01f * v;
    }
    __syncthreads();

    // heads: [32,256] @ [256,128]
    float acc2[4][4];
#pragma unroll
    for (int i = 0; i < 4; i++)
#pragma unroll
        for (int j = 0; j < 4; j++) acc2[i][j] = 0.f;

    for (int k0 = 0; k0 < H; k0 += KC) {
#pragma unroll
        for (int q = 0; q < 2; q++) {
            int f4 = t + 256 * q, row = f4 >> 5, c4 = f4 & 31;
            *reinterpret_cast<float4*>(&Ws0[row * HEADN + c4 * 4]) =
                *reinterpret_cast<const float4*>(&g_whead[(size_t)(k0 + row) * HEADN + c4 * 4]);
        }
        __syncthreads();
#pragma unroll
        for (int kk = 0; kk < KC; kk++) {
            float4 av = *reinterpret_cast<const float4*>(&Hs[(k0 + kk) * HS_PITCH + w * 4]);
            float a[4] = {av.x, av.y, av.z, av.w};
#pragma unroll
            for (int j = 0; j < 4; j++) {
                float wt = Ws0[kk * HEADN + tn + 32 * j];
#pragma unroll
                for (int i = 0; i < 4; i++)
                    acc2[i][j] = fmaf(a[i], wt, acc2[i][j]);
            }
        }
        __syncthreads();
    }

#pragma unroll
    for (int j = 0; j < 4; j++) {
        const int c = tn + 32 * j;
        const float bias = (c < 64) ? b_pi[c] : b_vf[c - 64];
#pragma unroll
        for (int ri = 0; ri < 4; ri++) {
            const int row = w * 4 + ri;
            float y = acc2[ri][j] + bias;
            y = (y >= 0.f) ? y : 0.01f * y;
            size_t o = (c < 64)
                ? ((size_t)(b0 + row) * 64 + c)
                : ((size_t)Btot * 64 + (size_t)(b0 + row) * 64 + (c - 64));
            out[o] = y;
        }
    }
}

// ---------------- launch ----------------
extern "C" void kernel_launch(void* const* d_in, const int* in_sizes, int n_in,
                              void* d_out, int out_size) {
    const float* feats = (const float*)d_in[0];
    const float* w_ih  = (const float*)d_in[1];
    const float* w_hh  = (const float*)d_in[2];
    const float* b_ih  = (const float*)d_in[3];
    const float* b_hh  = (const float*)d_in[4];
    const float* w_pi  = (const float*)d_in[5];
    const float* b_pi  = (const float*)d_in[6];
    const float* w_vf  = (const float*)d_in[7];
    const float* b_vf  = (const float*)d_in[8];
    float* out = (float*)d_out;

    const int Btot   = out_size / 128;
    const int Tsteps = in_sizes[0] / (Btot * FD);
    const int rows   = Btot * Tsteps;

    const size_t smem2 = (size_t)(H * HS_PITCH + 2 * KC * G3) * sizeof(float); // ~132 KB
    const size_t smemX = (size_t)(2 * 128 * XP) * sizeof(uint32_t);            // ~132 KB
    cudaFuncSetAttribute(gru_recur, cudaFuncAttributeMaxDynamicSharedMemorySize, (int)smem2);
    cudaFuncSetAttribute(xgates_mma_sync, cudaFuncAttributeMaxDynamicSharedMemorySize, (int)smemX);

    pack_weights<<<64, 256>>>(w_hh, w_pi, w_vf);
    xgates_mma_sync<<<dim3(rows / 128, G3 / 128), 256, smemX>>>(feats, w_ih, b_ih);
    gru_recur<<<Btot / 32, 256, smem2>>>(b_hh, b_pi, b_vf, out, Btot, Tsteps);
}

// round 10
// speedup vs baseline: 1.7284x; 1.7284x over previous
#include <cuda_runtime.h>
#include <cuda_bf16.h>
#include <math.h>
#include <stdint.h>

#define H 256
#define G3 768
#define FD 128
#define HEADN 128
#define HS_PITCH 36
#define XP 132            // padded SMEM pitch for xgates mma tiles

typedef unsigned long long ull;

__device__ __forceinline__ void cp16(void* smem_dst, const void* gsrc) {
    unsigned d = (unsigned)__cvta_generic_to_shared(smem_dst);
    asm volatile("cp.async.cg.shared.global [%0], [%1], 16;" :: "r"(d), "l"(gsrc));
}
#define CP_COMMIT asm volatile("cp.async.commit_group;")
#define CP_WAIT0  asm volatile("cp.async.wait_group 0;")

__device__ __forceinline__ uint32_t f2tf32(float f) {
    uint32_t o;
    asm("cvt.rna.tf32.f32 %0, %1;" : "=r"(o) : "f"(f));
    return o;
}

// mma.sync m16n8k8 tf32 (A row-major, B col-major), acc in-place
#define MMA_TF32(c, a, b) \
    asm volatile("mma.sync.aligned.m16n8k8.row.col.f32.tf32.tf32.f32 " \
        "{%0,%1,%2,%3}, {%4,%5,%6,%7}, {%8,%9}, {%0,%1,%2,%3};" \
        : "+f"((c)[0]), "+f"((c)[1]), "+f"((c)[2]), "+f"((c)[3]) \
        : "r"((a)[0]), "r"((a)[1]), "r"((a)[2]), "r"((a)[3]), \
          "r"((b)[0]), "r"((b)[1]))

// mma.sync m16n8k16 bf16 (A row-major, B col-major), acc in-place
#define MMA_BF16(c, a, b) \
    asm volatile("mma.sync.aligned.m16n8k16.row.col.f32.bf16.bf16.f32 " \
        "{%0,%1,%2,%3}, {%4,%5,%6,%7}, {%8,%9}, {%0,%1,%2,%3};" \
        : "+f"((c)[0]), "+f"((c)[1]), "+f"((c)[2]), "+f"((c)[3]) \
        : "r"((a)[0]), "r"((a)[1]), "r"((a)[2]), "r"((a)[3]), \
          "r"((b)[0]), "r"((b)[1]))

__device__ __forceinline__ float sigf(float x) {
    return __fdividef(1.f, 1.f + __expf(-x));
}
__device__ __forceinline__ float tanhfast(float x) {
    return 1.f - __fdividef(2.f, __expf(2.f * x) + 1.f);   // saturation-safe
}

// ---------------- scratch ----------------
__device__ float g_xg[4096UL * 64UL * 768UL];
__device__ float g_whead[H * HEADN];
// w_hh split bf16 hi/lo, column-reordered n' = (hid/8)*24 + gate*8 + hid%8,
// chunked [16 k16-chunks][2 k8-halves][768 n'][8 bf16]
__device__ __nv_bfloat16 g_wbhi[16 * 2 * 768 * 8];
__device__ __nv_bfloat16 g_wblo[16 * 2 * 768 * 8];

// ---------------- kernel 0: pack ----------------
__global__ void pack_weights(const float* __restrict__ w_hh,
                             const float* __restrict__ w_pi,
                             const float* __restrict__ w_vf) {
    int idx = blockIdx.x * blockDim.x + threadIdx.x;
    int stride = gridDim.x * blockDim.x;
    for (int i = idx; i < G3 * H; i += stride) {
        int grow = i >> 8, k = i & 255;
        int gate = grow >> 8, hid = grow & 255;
        int np = (hid >> 3) * 24 + gate * 8 + (hid & 7);
        int c = k >> 4, hf = (k >> 3) & 1, e = k & 7;
        float v = w_hh[grow * H + k];
        __nv_bfloat16 bh = __float2bfloat16(v);
        __nv_bfloat16 bl = __float2bfloat16(v - __bfloat162float(bh));
        size_t d = ((size_t)(c * 2 + hf) * 768 + np) * 8 + e;
        g_wbhi[d] = bh;
        g_wblo[d] = bl;
    }
    for (int i = idx; i < H * HEADN; i += stride) {
        int k = i / HEADN, j = i % HEADN;
        g_whead[i] = (j < 64) ? w_pi[j * H + k] : w_vf[(j - 64) * H + k];
    }
}

// ---------------- kernel 1: x_gates via mma.sync tf32 (unchanged, passing) ----------------
__global__ __launch_bounds__(256, 1) void xgates_mma_sync(const float* __restrict__ feats,
                                                          const float* __restrict__ w_ih,
                                                          const float* __restrict__ b_ih) {
    extern __shared__ uint32_t xs[];
    uint32_t* As = xs;                 // [128][XP]
    uint32_t* Bs = xs + 128 * XP;      // [128][XP]

    const int t = threadIdx.x;
    const int lane = t & 31;
    const int w = t >> 5;
    const int wm = w & 1;
    const int wn = w >> 1;
    const int m0 = blockIdx.x * 128;
    const int n0 = blockIdx.y * 128;

#pragma unroll
    for (int q = 0; q < 16; q++) {
        int idx = t + 256 * q, row = idx >> 5, c4 = idx & 31;
        float4 va = *reinterpret_cast<const float4*>(
            &feats[(size_t)(m0 + row) * FD + c4 * 4]);
        uint4 ua = {f2tf32(va.x), f2tf32(va.y), f2tf32(va.z), f2tf32(va.w)};
        *reinterpret_cast<uint4*>(&As[row * XP + c4 * 4]) = ua;
        float4 vb = *reinterpret_cast<const float4*>(
            &w_ih[(size_t)(n0 + row) * FD + c4 * 4]);
        uint4 ub = {f2tf32(vb.x), f2tf32(vb.y), f2tf32(vb.z), f2tf32(vb.w)};
        *reinterpret_cast<uint4*>(&Bs[row * XP + c4 * 4]) = ub;
    }
    __syncthreads();

    float acc[16][4];
#pragma unroll
    for (int i = 0; i < 16; i++)
#pragma unroll
        for (int j = 0; j < 4; j++) acc[i][j] = 0.f;

    const int rA = wm * 64 + (lane >> 2);
    const int rB = wn * 32 + (lane >> 2);
    const int kl = lane & 3;

#pragma unroll
    for (int ks = 0; ks < 16; ks++) {
        const int k0 = ks * 8 + kl;
        uint32_t a[4][4], b[4][2];
#pragma unroll
        for (int mt = 0; mt < 4; mt++) {
            const int r = rA + mt * 16;
            a[mt][0] = As[r * XP + k0];
            a[mt][1] = As[(r + 8) * XP + k0];
            a[mt][2] = As[r * XP + k0 + 4];
            a[mt][3] = As[(r + 8) * XP + k0 + 4];
        }
#pragma unroll
        for (int nt = 0; nt < 4; nt++) {
            const int n = rB + nt * 8;
            b[nt][0] = Bs[n * XP + k0];
            b[nt][1] = Bs[n * XP + k0 + 4];
        }
#pragma unroll
        for (int mt = 0; mt < 4; mt++)
#pragma unroll
            for (int nt = 0; nt < 4; nt++)
                MMA_TF32(acc[mt * 4 + nt], a[mt], b[nt]);
    }

#pragma unroll
    for (int nt = 0; nt < 4; nt++) {
        const int col = n0 + wn * 32 + nt * 8 + 2 * kl;
        const float bx = b_ih[col], by = b_ih[col + 1];
#pragma unroll
        for (int mt = 0; mt < 4; mt++) {
            const int r = m0 + wm * 64 + mt * 16 + (lane >> 2);
            float2 v0 = {acc[mt * 4 + nt][0] + bx, acc[mt * 4 + nt][1] + by};
            float2 v1 = {acc[mt * 4 + nt][2] + bx, acc[mt * 4 + nt][3] + by};
            *reinterpret_cast<float2*>(&g_xg[(size_t)r * G3 + col]) = v0;
            *reinterpret_cast<float2*>(&g_xg[(size_t)(r + 8) * G3 + col]) = v1;
        }
    }
}

// ---------------- kernel 2: GRU recurrence via mma.sync bf16 3-pass ----------------
// CTA owns 32 batch rows. Per step: hg[32][768'] = h[32][256] @ W'^T via
// m16n8k16 bf16 (A = h split hi/lo, B = w_hh split hi/lo, 3 passes).
// Warp wid owns n'-tiles [12*wid, 12*wid+12) = hidden units [32*wid, 32*wid+32)
// for all 3 gates. Thread (gid=lane/4, tig=lane%4) owns rows {gid,+8,+16,+24}
// x hidden pairs (4w+b)*8 + 2*tig for b=0..3 -> gate combine is thread-local.
#define SM_W0 0
#define SM_W1 49152
#define SM_AH 98304
#define SM_AL (98304 + 16384)
#define SM_HS 131072
#define SM_TOT (131072 + 36864)
#define WCHUNK 24576     // bytes of one (hi or lo) weight chunk

__device__ __forceinline__ void load_wchunk(char* dst, int c, int t) {
    const char* sh = (const char*)g_wbhi + (size_t)c * WCHUNK;
    const char* sl = (const char*)g_wblo + (size_t)c * WCHUNK;
#pragma unroll
    for (int q = 0; q < 12; q++) {
        int u = t + 256 * q;                     // 3072 x 16B = 48KB
        if (u < 1536) cp16(dst + u * 16, sh + u * 16);
        else          cp16(dst + u * 16, sl + (u - 1536) * 16);
    }
}

__global__ __launch_bounds__(256) void gru_recur(const float* __restrict__ b_hh,
                                                 const float* __restrict__ b_pi,
                                                 const float* __restrict__ b_vf,
                                                 float* __restrict__ out,
                                                 int Btot, int Tsteps) {
    extern __shared__ char smem[];
    float* Hs = reinterpret_cast<float*>(smem + SM_HS);     // [256][36] : Hs[hid][row]
    uint32_t* AHu = reinterpret_cast<uint32_t*>(smem + SM_AH);
    uint32_t* ALu = reinterpret_cast<uint32_t*>(smem + SM_AL);

    const int t = threadIdx.x;
    const int lane = t & 31;
    const int wid = t >> 5;
    const int gid = lane >> 2;
    const int tig = lane & 3;
    const int b0 = blockIdx.x * 32;

    // hoisted gate biases for this thread's hidden pairs
    float2 bR[4], bZ[4], bN[4];
#pragma unroll
    for (int b = 0; b < 4; b++) {
        const int hid0 = (4 * wid + b) * 8 + tig * 2;
        bR[b] = *reinterpret_cast<const float2*>(&b_hh[hid0]);
        bZ[b] = *reinterpret_cast<const float2*>(&b_hh[H + hid0]);
        bN[b] = *reinterpret_cast<const float2*>(&b_hh[2 * H + hid0]);
    }

    for (int i = t; i < H * HS_PITCH; i += 256) Hs[i] = 0.f;
    __syncthreads();

    for (int st = 0; st < Tsteps; st++) {
        // prefetch chunk 0 (overlaps A-build); buffers were quiesced by step-end sync
        load_wchunk(smem + SM_W0, 0, t);
        CP_COMMIT;

        // A-build: split h -> bf16 hi/lo planes [chunk][half][row][8]
        {
            const int hg = t >> 5;               // hidden group: 32 hids
#pragma unroll
            for (int j = 0; j < 16; j++) {
                const int hid0 = hg * 32 + 2 * j;
                float v0 = Hs[hid0 * HS_PITCH + lane];
                float v1 = Hs[(hid0 + 1) * HS_PITCH + lane];
                __nv_bfloat162 hi2;
                hi2.x = __float2bfloat16(v0);
                hi2.y = __float2bfloat16(v1);
                __nv_bfloat162 lo2;
                lo2.x = __float2bfloat16(v0 - __bfloat162float(hi2.x));
                lo2.y = __float2bfloat16(v1 - __bfloat162float(hi2.y));
                const int c = hid0 >> 4, hf = (hid0 >> 3) & 1, e = hid0 & 7;
                const int idx = ((c * 2 + hf) * 32 + lane) * 4 + (e >> 1);
                *reinterpret_cast<__nv_bfloat162*>(&AHu[idx]) = hi2;
                *reinterpret_cast<__nv_bfloat162*>(&ALu[idx]) = lo2;
            }
        }

        float acc[2][12][4];
#pragma unroll
        for (int m = 0; m < 2; m++)
#pragma unroll
            for (int nt = 0; nt < 12; nt++)
#pragma unroll
                for (int j = 0; j < 4; j++) acc[m][nt][j] = 0.f;

        for (int c = 0; c < 16; c++) {
            CP_WAIT0;
            __syncthreads();                     // chunk c resident; prev reads done
            if (c + 1 < 16) {
                load_wchunk(smem + ((c + 1) & 1 ? SM_W1 : SM_W0), c + 1, t);
                CP_COMMIT;
            }
            const char* Wc = smem + ((c & 1) ? SM_W1 : SM_W0);
            const uint32_t* Wh = reinterpret_cast<const uint32_t*>(Wc);
            const uint32_t* Wl = reinterpret_cast<const uint32_t*>(Wc + WCHUNK);
            const uint32_t* Ah = AHu + c * 256;
            const uint32_t* Al = ALu + c * 256;

            uint32_t ah[2][4], al[2][4];
#pragma unroll
            for (int m = 0; m < 2; m++) {
                const int base = gid + m * 16;
                ah[m][0] = Ah[base * 4 + tig];
                ah[m][1] = Ah[(base + 8) * 4 + tig];
                ah[m][2] = Ah[128 + base * 4 + tig];
                ah[m][3] = Ah[128 + (base + 8) * 4 + tig];
                al[m][0] = Al[base * 4 + tig];
                al[m][1] = Al[(base + 8) * 4 + tig];
                al[m][2] = Al[128 + base * 4 + tig];
                al[m][3] = Al[128 + (base + 8) * 4 + tig];
            }
#pragma unroll
            for (int nt = 0; nt < 12; nt++) {
                const int n = (wid * 12 + nt) * 8 + gid;
                uint32_t bh[2], bl[2];
                bh[0] = Wh[n * 4 + tig];
                bh[1] = Wh[3072 + n * 4 + tig];
                bl[0] = Wl[n * 4 + tig];
                bl[1] = Wl[3072 + n * 4 + tig];
                MMA_BF16(acc[0][nt], ah[0], bh);
                MMA_BF16(acc[1][nt], ah[1], bh);
                MMA_BF16(acc[0][nt], al[0], bh);
                MMA_BF16(acc[1][nt], al[1], bh);
                MMA_BF16(acc[0][nt], ah[0], bl);
                MMA_BF16(acc[1][nt], ah[1], bl);
            }
        }

        // gate epilogue: thread-local r/z/n combine + h update
#pragma unroll
        for (int m = 0; m < 2; m++)
#pragma unroll
            for (int rr = 0; rr < 2; rr++) {
                const int row = gid + m * 16 + rr * 8;
                const size_t gro = ((size_t)(b0 + row) * Tsteps + st) * (size_t)G3;
#pragma unroll
                for (int b = 0; b < 4; b++) {
                    const int hid0 = (4 * wid + b) * 8 + tig * 2;
                    const float2 xr = *reinterpret_cast<const float2*>(&g_xg[gro + hid0]);
                    const float2 xz = *reinterpret_cast<const float2*>(&g_xg[gro + H + hid0]);
                    const float2 xn = *reinterpret_cast<const float2*>(&g_xg[gro + 2 * H + hid0]);
                    const float hr0 = acc[m][b * 3 + 0][rr * 2];
                    const float hr1 = acc[m][b * 3 + 0][rr * 2 + 1];
                    const float hz0 = acc[m][b * 3 + 1][rr * 2];
                    const float hz1 = acc[m][b * 3 + 1][rr * 2 + 1];
                    const float hn0 = acc[m][b * 3 + 2][rr * 2];
                    const float hn1 = acc[m][b * 3 + 2][rr * 2 + 1];
                    {
                        const float r = sigf(xr.x + hr0 + bR[b].x);
                        const float z = sigf(xz.x + hz0 + bZ[b].x);
                        const float n = tanhfast(xn.x + r * (hn0 + bN[b].x));
                        const float hold = Hs[hid0 * HS_PITCH + row];
                        Hs[hid0 * HS_PITCH + row] = (1.f - z) * n + z * hold;
                    }
                    {
                        const float r = sigf(xr.y + hr1 + bR[b].y);
                        const float z = sigf(xz.y + hz1 + bZ[b].y);
                        const float n = tanhfast(xn.y + r * (hn1 + bN[b].y));
                        const float hold = Hs[(hid0 + 1) * HS_PITCH + row];
                        Hs[(hid0 + 1) * HS_PITCH + row] = (1.f - z) * n + z * hold;
                    }
                }
            }
        __syncthreads();                         // Hs complete before next A-build
    }

    // LeakyReLU on final h
    for (int idx = t; idx < H * 32; idx += 256) {
        const int hid = idx >> 5, row = idx & 31;
        float v = Hs[hid * HS_PITCH + row];
        Hs[hid * HS_PITCH + row] = (v >= 0.f) ? v : 0.01f * v;
    }
    __syncthreads();

    // heads: [32,256] @ [256,128] (fp32 scalar, reuse W buffer region)
    float* Ws0 = reinterpret_cast<float*>(smem);
    float acc2[4][4];
#pragma unroll
    for (int i = 0; i < 4; i++)
#pragma unroll
        for (int j = 0; j < 4; j++) acc2[i][j] = 0.f;

    for (int k0 = 0; k0 < H; k0 += 16) {
#pragma unroll
        for (int q = 0; q < 2; q++) {
            int f4 = t + 256 * q, row = f4 >> 5, c4 = f4 & 31;
            *reinterpret_cast<float4*>(&Ws0[row * HEADN + c4 * 4]) =
                *reinterpret_cast<const float4*>(&g_whead[(size_t)(k0 + row) * HEADN + c4 * 4]);
        }
        __syncthreads();
#pragma unroll
        for (int kk = 0; kk < 16; kk++) {
            float4 av = *reinterpret_cast<const float4*>(&Hs[(k0 + kk) * HS_PITCH + wid * 4]);
            float a[4] = {av.x, av.y, av.z, av.w};
#pragma unroll
            for (int j = 0; j < 4; j++) {
                float wt = Ws0[kk * HEADN + lane + 32 * j];
#pragma unroll
                for (int i = 0; i < 4; i++)
                    acc2[i][j] = fmaf(a[i], wt, acc2[i][j]);
            }
        }
        __syncthreads();
    }

#pragma unroll
    for (int j = 0; j < 4; j++) {
        const int c = lane + 32 * j;
        const float bias = (c < 64) ? b_pi[c] : b_vf[c - 64];
#pragma unroll
        for (int ri = 0; ri < 4; ri++) {
            const int row = wid * 4 + ri;
            float y = acc2[ri][j] + bias;
            y = (y >= 0.f) ? y : 0.01f * y;
            size_t o = (c < 64)
                ? ((size_t)(b0 + row) * 64 + c)
                : ((size_t)Btot * 64 + (size_t)(b0 + row) * 64 + (c - 64));
            out[o] = y;
        }
    }
}

// ---------------- launch ----------------
extern "C" void kernel_launch(void* const* d_in, const int* in_sizes, int n_in,
                              void* d_out, int out_size) {
    const float* feats = (const float*)d_in[0];
    const float* w_ih  = (const float*)d_in[1];
    const float* w_hh  = (const float*)d_in[2];
    const float* b_ih  = (const float*)d_in[3];
    const float* b_hh  = (const float*)d_in[4];
    const float* w_pi  = (const float*)d_in[5];
    const float* b_pi  = (const float*)d_in[6];
    const float* w_vf  = (const float*)d_in[7];
    const float* b_vf  = (const float*)d_in[8];
    float* out = (float*)d_out;

    const int Btot   = out_size / 128;
    const int Tsteps = in_sizes[0] / (Btot * FD);
    const int rows   = Btot * Tsteps;

    const size_t smemX = (size_t)(2 * 128 * XP) * sizeof(uint32_t);   // ~132 KB
    cudaFuncSetAttribute(xgates_mma_sync, cudaFuncAttributeMaxDynamicSharedMemorySize, (int)smemX);
    cudaFuncSetAttribute(gru_recur, cudaFuncAttributeMaxDynamicSharedMemorySize, SM_TOT);

    pack_weights<<<64, 256>>>(w_hh, w_pi, w_vf);
    xgates_mma_sync<<<dim3(rows / 128, G3 / 128), 256, smemX>>>(feats, w_ih, b_ih);
    gru_recur<<<Btot / 32, 256, SM_TOT>>>(b_hh, b_pi, b_vf, out, Btot, Tsteps);
}

// round 11
// speedup vs baseline: 1.7301x; 1.0010x over previous
#include <cuda_runtime.h>
#include <cuda_bf16.h>
#include <math.h>
#include <stdint.h>

#define H 256
#define G3 768
#define FD 128
#define HEADN 128
#define HS_PITCH 36
#define XP 132            // padded SMEM pitch for xgates mma tiles

typedef unsigned long long ull;

__device__ __forceinline__ void cp16(void* smem_dst, const void* gsrc) {
    unsigned d = (unsigned)__cvta_generic_to_shared(smem_dst);
    asm volatile("cp.async.cg.shared.global [%0], [%1], 16;" :: "r"(d), "l"(gsrc));
}
#define CP_COMMIT asm volatile("cp.async.commit_group;")
#define CP_WAIT1  asm volatile("cp.async.wait_group 1;")
#define CP_WAIT0  asm volatile("cp.async.wait_group 0;")

__device__ __forceinline__ uint32_t f2tf32(float f) {
    uint32_t o;
    asm("cvt.rna.tf32.f32 %0, %1;" : "=r"(o) : "f"(f));
    return o;
}

// mma.sync m16n8k8 tf32 (A row-major, B col-major), acc in-place
#define MMA_TF32(c, a, b) \
    asm volatile("mma.sync.aligned.m16n8k8.row.col.f32.tf32.tf32.f32 " \
        "{%0,%1,%2,%3}, {%4,%5,%6,%7}, {%8,%9}, {%0,%1,%2,%3};" \
        : "+f"((c)[0]), "+f"((c)[1]), "+f"((c)[2]), "+f"((c)[3]) \
        : "r"((a)[0]), "r"((a)[1]), "r"((a)[2]), "r"((a)[3]), \
          "r"((b)[0]), "r"((b)[1]))

// mma.sync m16n8k16 bf16 (A row-major, B col-major), acc in-place
#define MMA_BF16(c, a, b) \
    asm volatile("mma.sync.aligned.m16n8k16.row.col.f32.bf16.bf16.f32 " \
        "{%0,%1,%2,%3}, {%4,%5,%6,%7}, {%8,%9}, {%0,%1,%2,%3};" \
        : "+f"((c)[0]), "+f"((c)[1]), "+f"((c)[2]), "+f"((c)[3]) \
        : "r"((a)[0]), "r"((a)[1]), "r"((a)[2]), "r"((a)[3]), \
          "r"((b)[0]), "r"((b)[1]))

__device__ __forceinline__ float sigf(float x) {
    return __fdividef(1.f, 1.f + __expf(-x));
}
__device__ __forceinline__ float tanhfast(float x) {
    return 1.f - __fdividef(2.f, __expf(2.f * x) + 1.f);   // saturation-safe
}

// ---------------- scratch ----------------
__device__ float g_xg[4096UL * 64UL * 768UL];
__device__ float g_whead[H * HEADN];
// w_hh split bf16 hi/lo, column-reordered n' = (hid/8)*24 + gate*8 + hid%8,
// chunked [16 k16-chunks][2 k8-halves][768 n'][8 bf16]
__device__ __nv_bfloat16 g_wbhi[16 * 2 * 768 * 8];
__device__ __nv_bfloat16 g_wblo[16 * 2 * 768 * 8];

// ---------------- kernel 0: pack ----------------
__global__ void pack_weights(const float* __restrict__ w_hh,
                             const float* __restrict__ w_pi,
                             const float* __restrict__ w_vf) {
    int idx = blockIdx.x * blockDim.x + threadIdx.x;
    int stride = gridDim.x * blockDim.x;
    for (int i = idx; i < G3 * H; i += stride) {
        int grow = i >> 8, k = i & 255;
        int gate = grow >> 8, hid = grow & 255;
        int np = (hid >> 3) * 24 + gate * 8 + (hid & 7);
        int c = k >> 4, hf = (k >> 3) & 1, e = k & 7;
        float v = w_hh[grow * H + k];
        __nv_bfloat16 bh = __float2bfloat16(v);
        __nv_bfloat16 bl = __float2bfloat16(v - __bfloat162float(bh));
        size_t d = ((size_t)(c * 2 + hf) * 768 + np) * 8 + e;
        g_wbhi[d] = bh;
        g_wblo[d] = bl;
    }
    for (int i = idx; i < H * HEADN; i += stride) {
        int k = i / HEADN, j = i % HEADN;
        g_whead[i] = (j < 64) ? w_pi[j * H + k] : w_vf[(j - 64) * H + k];
    }
}

// ---------------- kernel 1: x_gates via mma.sync tf32 (unchanged, passing) ----------------
__global__ __launch_bounds__(256, 1) void xgates_mma_sync(const float* __restrict__ feats,
                                                          const float* __restrict__ w_ih,
                                                          const float* __restrict__ b_ih) {
    extern __shared__ uint32_t xs[];
    uint32_t* As = xs;                 // [128][XP]
    uint32_t* Bs = xs + 128 * XP;      // [128][XP]

    const int t = threadIdx.x;
    const int lane = t & 31;
    const int w = t >> 5;
    const int wm = w & 1;
    const int wn = w >> 1;
    const int m0 = blockIdx.x * 128;
    const int n0 = blockIdx.y * 128;

#pragma unroll
    for (int q = 0; q < 16; q++) {
        int idx = t + 256 * q, row = idx >> 5, c4 = idx & 31;
        float4 va = *reinterpret_cast<const float4*>(
            &feats[(size_t)(m0 + row) * FD + c4 * 4]);
        uint4 ua = {f2tf32(va.x), f2tf32(va.y), f2tf32(va.z), f2tf32(va.w)};
        *reinterpret_cast<uint4*>(&As[row * XP + c4 * 4]) = ua;
        float4 vb = *reinterpret_cast<const float4*>(
            &w_ih[(size_t)(n0 + row) * FD + c4 * 4]);
        uint4 ub = {f2tf32(vb.x), f2tf32(vb.y), f2tf32(vb.z), f2tf32(vb.w)};
        *reinterpret_cast<uint4*>(&Bs[row * XP + c4 * 4]) = ub;
    }
    __syncthreads();

    float acc[16][4];
#pragma unroll
    for (int i = 0; i < 16; i++)
#pragma unroll
        for (int j = 0; j < 4; j++) acc[i][j] = 0.f;

    const int rA = wm * 64 + (lane >> 2);
    const int rB = wn * 32 + (lane >> 2);
    const int kl = lane & 3;

#pragma unroll
    for (int ks = 0; ks < 16; ks++) {
        const int k0 = ks * 8 + kl;
        uint32_t a[4][4], b[4][2];
#pragma unroll
        for (int mt = 0; mt < 4; mt++) {
            const int r = rA + mt * 16;
            a[mt][0] = As[r * XP + k0];
            a[mt][1] = As[(r + 8) * XP + k0];
            a[mt][2] = As[r * XP + k0 + 4];
            a[mt][3] = As[(r + 8) * XP + k0 + 4];
        }
#pragma unroll
        for (int nt = 0; nt < 4; nt++) {
            const int n = rB + nt * 8;
            b[nt][0] = Bs[n * XP + k0];
            b[nt][1] = Bs[n * XP + k0 + 4];
        }
#pragma unroll
        for (int mt = 0; mt < 4; mt++)
#pragma unroll
            for (int nt = 0; nt < 4; nt++)
                MMA_TF32(acc[mt * 4 + nt], a[mt], b[nt]);
    }

#pragma unroll
    for (int nt = 0; nt < 4; nt++) {
        const int col = n0 + wn * 32 + nt * 8 + 2 * kl;
        const float bx = b_ih[col], by = b_ih[col + 1];
#pragma unroll
        for (int mt = 0; mt < 4; mt++) {
            const int r = m0 + wm * 64 + mt * 16 + (lane >> 2);
            float2 v0 = {acc[mt * 4 + nt][0] + bx, acc[mt * 4 + nt][1] + by};
            float2 v1 = {acc[mt * 4 + nt][2] + bx, acc[mt * 4 + nt][3] + by};
            *reinterpret_cast<float2*>(&g_xg[(size_t)r * G3 + col]) = v0;
            *reinterpret_cast<float2*>(&g_xg[(size_t)(r + 8) * G3 + col]) = v1;
        }
    }
}

// ---------------- kernel 2: GRU recurrence via mma.sync bf16 3-pass ----------------
// CTA owns 32 batch rows. Per step: hg[32][768'] = h[32][256] @ W'^T via
// m16n8k16 bf16 (A = h split hi/lo, B = w_hh split hi/lo, 3 passes).
// NEW vs R10: (1) chunk order staggered by blockIdx (decorrelates L2 slice
// bursts across CTAs; fp32 acc reorder only), (2) triple-buffered weight
// pipeline with wait_group 1 -> two 48KB chunk loads in flight.
#define SM_W0 0
#define SM_W1 49152
#define SM_W2 98304
#define SM_AH 147456
#define SM_AL (147456 + 16384)
#define SM_HS 180224
#define SM_TOT (180224 + 36864)     // 217088 B
#define WCHUNK 24576                 // bytes of one (hi or lo) weight chunk

__device__ __forceinline__ void load_wchunk(char* dst, int c, int t) {
    const char* sh = (const char*)g_wbhi + (size_t)c * WCHUNK;
    const char* sl = (const char*)g_wblo + (size_t)c * WCHUNK;
#pragma unroll
    for (int q = 0; q < 12; q++) {
        int u = t + 256 * q;                     // 3072 x 16B = 48KB
        if (u < 1536) cp16(dst + u * 16, sh + u * 16);
        else          cp16(dst + u * 16, sl + (u - 1536) * 16);
    }
}

__global__ __launch_bounds__(256) void gru_recur(const float* __restrict__ b_hh,
                                                 const float* __restrict__ b_pi,
                                                 const float* __restrict__ b_vf,
                                                 float* __restrict__ out,
                                                 int Btot, int Tsteps) {
    extern __shared__ char smem[];
    float* Hs = reinterpret_cast<float*>(smem + SM_HS);     // [256][36] : Hs[hid][row]
    uint32_t* AHu = reinterpret_cast<uint32_t*>(smem + SM_AH);
    uint32_t* ALu = reinterpret_cast<uint32_t*>(smem + SM_AL);

    const int t = threadIdx.x;
    const int lane = t & 31;
    const int wid = t >> 5;
    const int gid = lane >> 2;
    const int tig = lane & 3;
    const int b0 = blockIdx.x * 32;
    const int off = blockIdx.x & 15;             // chunk-order stagger
    const int WOFF0 = SM_W0, WOFF1 = SM_W1, WOFF2 = SM_W2;

    // hoisted gate biases for this thread's hidden pairs
    float2 bR[4], bZ[4], bN[4];
#pragma unroll
    for (int b = 0; b < 4; b++) {
        const int hid0 = (4 * wid + b) * 8 + tig * 2;
        bR[b] = *reinterpret_cast<const float2*>(&b_hh[hid0]);
        bZ[b] = *reinterpret_cast<const float2*>(&b_hh[H + hid0]);
        bN[b] = *reinterpret_cast<const float2*>(&b_hh[2 * H + hid0]);
    }

    for (int i = t; i < H * HS_PITCH; i += 256) Hs[i] = 0.f;
    __syncthreads();

    for (int st = 0; st < Tsteps; st++) {
        // issue first two chunk loads (prev step's final sync quiesced all buffers)
        load_wchunk(smem + WOFF0, (off + 0) & 15, t);
        CP_COMMIT;
        load_wchunk(smem + WOFF1, (off + 1) & 15, t);
        CP_COMMIT;

        // A-build: split h -> bf16 hi/lo planes [chunk][half][row][8]
        {
            const int hg = t >> 5;               // hidden group: 32 hids
#pragma unroll
            for (int j = 0; j < 16; j++) {
                const int hid0 = hg * 32 + 2 * j;
                float v0 = Hs[hid0 * HS_PITCH + lane];
                float v1 = Hs[(hid0 + 1) * HS_PITCH + lane];
                __nv_bfloat162 hi2;
                hi2.x = __float2bfloat16(v0);
                hi2.y = __float2bfloat16(v1);
                __nv_bfloat162 lo2;
                lo2.x = __float2bfloat16(v0 - __bfloat162float(hi2.x));
                lo2.y = __float2bfloat16(v1 - __bfloat162float(hi2.y));
                const int c = hid0 >> 4, hf = (hid0 >> 3) & 1, e = hid0 & 7;
                const int idx = ((c * 2 + hf) * 32 + lane) * 4 + (e >> 1);
                *reinterpret_cast<__nv_bfloat162*>(&AHu[idx]) = hi2;
                *reinterpret_cast<__nv_bfloat162*>(&ALu[idx]) = lo2;
            }
        }

        float acc[2][12][4];
#pragma unroll
        for (int m = 0; m < 2; m++)
#pragma unroll
            for (int nt = 0; nt < 12; nt++)
#pragma unroll
                for (int j = 0; j < 4; j++) acc[m][nt][j] = 0.f;

        for (int c = 0; c < 16; c++) {
            if (c + 2 < 16) { CP_WAIT1; } else { CP_WAIT0; }
            __syncthreads();                     // chunk c resident; buf (c+2)%3 quiesced
            if (c + 2 < 16) {
                const int wb = (c + 2) % 3;
                char* dst = smem + (wb == 0 ? WOFF0 : (wb == 1 ? WOFF1 : WOFF2));
                load_wchunk(dst, (off + c + 2) & 15, t);
                CP_COMMIT;
            }
            const int cc = (off + c) & 15;       // actual chunk index
            const int cb = c % 3;
            const char* Wc = smem + (cb == 0 ? WOFF0 : (cb == 1 ? WOFF1 : WOFF2));
            const uint32_t* Wh = reinterpret_cast<const uint32_t*>(Wc);
            const uint32_t* Wl = reinterpret_cast<const uint32_t*>(Wc + WCHUNK);
            const uint32_t* Ah = AHu + cc * 256;
            const uint32_t* Al = ALu + cc * 256;

            uint32_t ah[2][4], al[2][4];
#pragma unroll
            for (int m = 0; m < 2; m++) {
                const int base = gid + m * 16;
                ah[m][0] = Ah[base * 4 + tig];
                ah[m][1] = Ah[(base + 8) * 4 + tig];
                ah[m][2] = Ah[128 + base * 4 + tig];
                ah[m][3] = Ah[128 + (base + 8) * 4 + tig];
                al[m][0] = Al[base * 4 + tig];
                al[m][1] = Al[(base + 8) * 4 + tig];
                al[m][2] = Al[128 + base * 4 + tig];
                al[m][3] = Al[128 + (base + 8) * 4 + tig];
            }
#pragma unroll
            for (int nt = 0; nt < 12; nt++) {
                const int n = (wid * 12 + nt) * 8 + gid;
                uint32_t bh[2], bl[2];
                bh[0] = Wh[n * 4 + tig];
                bh[1] = Wh[3072 + n * 4 + tig];
                bl[0] = Wl[n * 4 + tig];
                bl[1] = Wl[3072 + n * 4 + tig];
                MMA_BF16(acc[0][nt], ah[0], bh);
                MMA_BF16(acc[1][nt], ah[1], bh);
                MMA_BF16(acc[0][nt], al[0], bh);
                MMA_BF16(acc[1][nt], al[1], bh);
                MMA_BF16(acc[0][nt], ah[0], bl);
                MMA_BF16(acc[1][nt], ah[1], bl);
            }
        }

        // gate epilogue: thread-local r/z/n combine + h update
#pragma unroll
        for (int m = 0; m < 2; m++)
#pragma unroll
            for (int rr = 0; rr < 2; rr++) {
                const int row = gid + m * 16 + rr * 8;
                const size_t gro = ((size_t)(b0 + row) * Tsteps + st) * (size_t)G3;
#pragma unroll
                for (int b = 0; b < 4; b++) {
                    const int hid0 = (4 * wid + b) * 8 + tig * 2;
                    const float2 xr = *reinterpret_cast<const float2*>(&g_xg[gro + hid0]);
                    const float2 xz = *reinterpret_cast<const float2*>(&g_xg[gro + H + hid0]);
                    const float2 xn = *reinterpret_cast<const float2*>(&g_xg[gro + 2 * H + hid0]);
                    const float hr0 = acc[m][b * 3 + 0][rr * 2];
                    const float hr1 = acc[m][b * 3 + 0][rr * 2 + 1];
                    const float hz0 = acc[m][b * 3 + 1][rr * 2];
                    const float hz1 = acc[m][b * 3 + 1][rr * 2 + 1];
                    const float hn0 = acc[m][b * 3 + 2][rr * 2];
                    const float hn1 = acc[m][b * 3 + 2][rr * 2 + 1];
                    {
                        const float r = sigf(xr.x + hr0 + bR[b].x);
                        const float z = sigf(xz.x + hz0 + bZ[b].x);
                        const float n = tanhfast(xn.x + r * (hn0 + bN[b].x));
                        const float hold = Hs[hid0 * HS_PITCH + row];
                        Hs[hid0 * HS_PITCH + row] = (1.f - z) * n + z * hold;
                    }
                    {
                        const float r = sigf(xr.y + hr1 + bR[b].y);
                        const float z = sigf(xz.y + hz1 + bZ[b].y);
                        const float n = tanhfast(xn.y + r * (hn1 + bN[b].y));
                        const float hold = Hs[(hid0 + 1) * HS_PITCH + row];
                        Hs[(hid0 + 1) * HS_PITCH + row] = (1.f - z) * n + z * hold;
                    }
                }
            }
        __syncthreads();                         // Hs complete; all buffers quiesced
    }

    // LeakyReLU on final h
    for (int idx = t; idx < H * 32; idx += 256) {
        const int hid = idx >> 5, row = idx & 31;
        float v = Hs[hid * HS_PITCH + row];
        Hs[hid * HS_PITCH + row] = (v >= 0.f) ? v : 0.01f * v;
    }
    __syncthreads();

    // heads: [32,256] @ [256,128] (fp32 scalar, reuse W buffer region)
    float* Ws0 = reinterpret_cast<float*>(smem);
    float acc2[4][4];
#pragma unroll
    for (int i = 0; i < 4; i++)
#pragma unroll
        for (int j = 0; j < 4; j++) acc2[i][j] = 0.f;

    for (int k0 = 0; k0 < H; k0 += 16) {
#pragma unroll
        for (int q = 0; q < 2; q++) {
            int f4 = t + 256 * q, row = f4 >> 5, c4 = f4 & 31;
            *reinterpret_cast<float4*>(&Ws0[row * HEADN + c4 * 4]) =
                *reinterpret_cast<const float4*>(&g_whead[(size_t)(k0 + row) * HEADN + c4 * 4]);
        }
        __syncthreads();
#pragma unroll
        for (int kk = 0; kk < 16; kk++) {
            float4 av = *reinterpret_cast<const float4*>(&Hs[(k0 + kk) * HS_PITCH + wid * 4]);
            float a[4] = {av.x, av.y, av.z, av.w};
#pragma unroll
            for (int j = 0; j < 4; j++) {
                float wt = Ws0[kk * HEADN + lane + 32 * j];
#pragma unroll
                for (int i = 0; i < 4; i++)
                    acc2[i][j] = fmaf(a[i], wt, acc2[i][j]);
            }
        }
        __syncthreads();
    }

#pragma unroll
    for (int j = 0; j < 4; j++) {
        const int c = lane + 32 * j;
        const float bias = (c < 64) ? b_pi[c] : b_vf[c - 64];
#pragma unroll
        for (int ri = 0; ri < 4; ri++) {
            const int row = wid * 4 + ri;
            float y = acc2[ri][j] + bias;
            y = (y >= 0.f) ? y : 0.01f * y;
            size_t o = (c < 64)
                ? ((size_t)(b0 + row) * 64 + c)
                : ((size_t)Btot * 64 + (size_t)(b0 + row) * 64 + (c - 64));
            out[o] = y;
        }
    }
}

// ---------------- launch ----------------
extern "C" void kernel_launch(void* const* d_in, const int* in_sizes, int n_in,
                              void* d_out, int out_size) {
    const float* feats = (const float*)d_in[0];
    const float* w_ih  = (const float*)d_in[1];
    const float* w_hh  = (const float*)d_in[2];
    const float* b_ih  = (const float*)d_in[3];
    const float* b_hh  = (const float*)d_in[4];
    const float* w_pi  = (const float*)d_in[5];
    const float* b_pi  = (const float*)d_in[6];
    const float* w_vf  = (const float*)d_in[7];
    const float* b_vf  = (const float*)d_in[8];
    float* out = (float*)d_out;

    const int Btot   = out_size / 128;
    const int Tsteps = in_sizes[0] / (Btot * FD);
    const int rows   = Btot * Tsteps;

    const size_t smemX = (size_t)(2 * 128 * XP) * sizeof(uint32_t);   // ~132 KB
    cudaFuncSetAttribute(xgates_mma_sync, cudaFuncAttributeMaxDynamicSharedMemorySize, (int)smemX);
    cudaFuncSetAttribute(gru_recur, cudaFuncAttributeMaxDynamicSharedMemorySize, SM_TOT);

    pack_weights<<<64, 256>>>(w_hh, w_pi, w_vf);
    xgates_mma_sync<<<dim3(rows / 128, G3 / 128), 256, smemX>>>(feats, w_ih, b_ih);
    gru_recur<<<Btot / 32, 256, SM_TOT>>>(b_hh, b_pi, b_vf, out, Btot, Tsteps);
}

// round 13
// speedup vs baseline: 1.9376x; 1.1200x over previous
#include <cuda_runtime.h>
#include <cuda_fp16.h>
#include <math.h>
#include <stdint.h>

#define H 256
#define G3 768
#define FD 128
#define HEADN 128
#define HS_PITCH 36
#define XP 132            // padded SMEM pitch for xgates mma tiles

typedef unsigned long long ull;

__device__ __forceinline__ void cp16(void* smem_dst, const void* gsrc) {
    unsigned d = (unsigned)__cvta_generic_to_shared(smem_dst);
    asm volatile("cp.async.cg.shared.global [%0], [%1], 16;" :: "r"(d), "l"(gsrc));
}
#define CP_COMMIT asm volatile("cp.async.commit_group;")
#define CP_WAIT1  asm volatile("cp.async.wait_group 1;")
#define CP_WAIT0  asm volatile("cp.async.wait_group 0;")

__device__ __forceinline__ uint32_t f2tf32(float f) {
    uint32_t o;
    asm("cvt.rna.tf32.f32 %0, %1;" : "=r"(o) : "f"(f));
    return o;
}

// mma.sync m16n8k8 tf32 (A row-major, B col-major), acc in-place
#define MMA_TF32(c, a, b) \
    asm volatile("mma.sync.aligned.m16n8k8.row.col.f32.tf32.tf32.f32 " \
        "{%0,%1,%2,%3}, {%4,%5,%6,%7}, {%8,%9}, {%0,%1,%2,%3};" \
        : "+f"((c)[0]), "+f"((c)[1]), "+f"((c)[2]), "+f"((c)[3]) \
        : "r"((a)[0]), "r"((a)[1]), "r"((a)[2]), "r"((a)[3]), \
          "r"((b)[0]), "r"((b)[1]))

// mma.sync m16n8k16 fp16 (A row-major, B col-major), fp32 acc in-place
#define MMA_F16(c, a, b) \
    asm volatile("mma.sync.aligned.m16n8k16.row.col.f32.f16.f16.f32 " \
        "{%0,%1,%2,%3}, {%4,%5,%6,%7}, {%8,%9}, {%0,%1,%2,%3};" \
        : "+f"((c)[0]), "+f"((c)[1]), "+f"((c)[2]), "+f"((c)[3]) \
        : "r"((a)[0]), "r"((a)[1]), "r"((a)[2]), "r"((a)[3]), \
          "r"((b)[0]), "r"((b)[1]))

__device__ __forceinline__ float sigf(float x) {
    return __fdividef(1.f, 1.f + __expf(-x));
}
__device__ __forceinline__ float tanhfast(float x) {
    return 1.f - __fdividef(2.f, __expf(2.f * x) + 1.f);   // saturation-safe
}

// ---------------- scratch ----------------
__device__ float g_xg[4096UL * 64UL * 768UL];
__device__ float g_whead[H * HEADN];
// w_hh split fp16 hi/lo (hi = rn(w), lo = rn(w - hi); together ~21 bits exact),
// column-reordered n' = (hid/8)*24 + gate*8 + hid%8,
// chunked [16 k16-chunks][2 k8-halves][768 n'][8 fp16]
__device__ __half g_wfhi[16 * 2 * 768 * 8];
__device__ __half g_wflo[16 * 2 * 768 * 8];

// ---------------- kernel 0: pack ----------------
__global__ void pack_weights(const float* __restrict__ w_hh,
                             const float* __restrict__ w_pi,
                             const float* __restrict__ w_vf) {
    int idx = blockIdx.x * blockDim.x + threadIdx.x;
    int stride = gridDim.x * blockDim.x;
    for (int i = idx; i < G3 * H; i += stride) {
        int grow = i >> 8, k = i & 255;
        int gate = grow >> 8, hid = grow & 255;
        int np = (hid >> 3) * 24 + gate * 8 + (hid & 7);
        int c = k >> 4, hf = (k >> 3) & 1, e = k & 7;
        float v = w_hh[grow * H + k];
        __half wh = __float2half_rn(v);
        __half wl = __float2half_rn(v - __half2float(wh));
        size_t d = ((size_t)(c * 2 + hf) * 768 + np) * 8 + e;
        g_wfhi[d] = wh;
        g_wflo[d] = wl;
    }
    for (int i = idx; i < H * HEADN; i += stride) {
        int k = i / HEADN, j = i % HEADN;
        g_whead[i] = (j < 64) ? w_pi[j * H + k] : w_vf[(j - 64) * H + k];
    }
}

// ---------------- kernel 1: x_gates via mma.sync tf32 (unchanged, passing) ----------------
__global__ __launch_bounds__(256, 1) void xgates_mma_sync(const float* __restrict__ feats,
                                                          const float* __restrict__ w_ih,
                                                          const float* __restrict__ b_ih) {
    extern __shared__ uint32_t xs[];
    uint32_t* As = xs;                 // [128][XP]
    uint32_t* Bs = xs + 128 * XP;      // [128][XP]

    const int t = threadIdx.x;
    const int lane = t & 31;
    const int w = t >> 5;
    const int wm = w & 1;
    const int wn = w >> 1;
    const int m0 = blockIdx.x * 128;
    const int n0 = blockIdx.y * 128;

#pragma unroll
    for (int q = 0; q < 16; q++) {
        int idx = t + 256 * q, row = idx >> 5, c4 = idx & 31;
        float4 va = *reinterpret_cast<const float4*>(
            &feats[(size_t)(m0 + row) * FD + c4 * 4]);
        uint4 ua = {f2tf32(va.x), f2tf32(va.y), f2tf32(va.z), f2tf32(va.w)};
        *reinterpret_cast<uint4*>(&As[row * XP + c4 * 4]) = ua;
        float4 vb = *reinterpret_cast<const float4*>(
            &w_ih[(size_t)(n0 + row) * FD + c4 * 4]);
        uint4 ub = {f2tf32(vb.x), f2tf32(vb.y), f2tf32(vb.z), f2tf32(vb.w)};
        *reinterpret_cast<uint4*>(&Bs[row * XP + c4 * 4]) = ub;
    }
    __syncthreads();

    float acc[16][4];
#pragma unroll
    for (int i = 0; i < 16; i++)
#pragma unroll
        for (int j = 0; j < 4; j++) acc[i][j] = 0.f;

    const int rA = wm * 64 + (lane >> 2);
    const int rB = wn * 32 + (lane >> 2);
    const int kl = lane & 3;

#pragma unroll
    for (int ks = 0; ks < 16; ks++) {
        const int k0 = ks * 8 + kl;
        uint32_t a[4][4], b[4][2];
#pragma unroll
        for (int mt = 0; mt < 4; mt++) {
            const int r = rA + mt * 16;
            a[mt][0] = As[r * XP + k0];
            a[mt][1] = As[(r + 8) * XP + k0];
            a[mt][2] = As[r * XP + k0 + 4];
            a[mt][3] = As[(r + 8) * XP + k0 + 4];
        }
#pragma unroll
        for (int nt = 0; nt < 4; nt++) {
            const int n = rB + nt * 8;
            b[nt][0] = Bs[n * XP + k0];
            b[nt][1] = Bs[n * XP + k0 + 4];
        }
#pragma unroll
        for (int mt = 0; mt < 4; mt++)
#pragma unroll
            for (int nt = 0; nt < 4; nt++)
                MMA_TF32(acc[mt * 4 + nt], a[mt], b[nt]);
    }

#pragma unroll
    for (int nt = 0; nt < 4; nt++) {
        const int col = n0 + wn * 32 + nt * 8 + 2 * kl;
        const float bx = b_ih[col], by = b_ih[col + 1];
#pragma unroll
        for (int mt = 0; mt < 4; mt++) {
            const int r = m0 + wm * 64 + mt * 16 + (lane >> 2);
            float2 v0 = {acc[mt * 4 + nt][0] + bx, acc[mt * 4 + nt][1] + by};
            float2 v1 = {acc[mt * 4 + nt][2] + bx, acc[mt * 4 + nt][3] + by};
            *reinterpret_cast<float2*>(&g_xg[(size_t)r * G3 + col]) = v0;
            *reinterpret_cast<float2*>(&g_xg[(size_t)(r + 8) * G3 + col]) = v1;
        }
    }
}

// ---------------- kernel 2: GRU recurrence via mma.sync fp16 2-pass ----------------
// CTA owns 32 batch rows. Per step: hg[32][768'] = h[32][256] @ W'^T via
// m16n8k16 fp16: A = h in fp16 (single plane), B = W exact as fp16 hi+lo.
// Passes: ah*wh + ah*wl -> 48 MMAs/warp/chunk (was 72 with bf16 3-pass).
// Warp wid owns n'-tiles [12*wid, 12*wid+12) = hidden units [32*wid, 32*wid+32)
// for all 3 gates; thread-local gate combine (nt = b*3 + gate).
#define SM_W0 0
#define SM_W1 49152
#define SM_W2 98304
#define SM_A  147456
#define SM_HS 163840
#define SM_TOT (163840 + 36864)     // 200704 B
#define WCHUNK 24576                 // bytes of one (hi or lo) weight chunk

__device__ __forceinline__ void load_wchunk(char* dst, int c, int t) {
    const char* sh = (const char*)g_wfhi + (size_t)c * WCHUNK;
    const char* sl = (const char*)g_wflo + (size_t)c * WCHUNK;
#pragma unroll
    for (int q = 0; q < 12; q++) {
        int u = t + 256 * q;                     // 3072 x 16B = 48KB
        if (u < 1536) cp16(dst + u * 16, sh + u * 16);
        else          cp16(dst + u * 16, sl + (u - 1536) * 16);
    }
}

__global__ __launch_bounds__(256) void gru_recur(const float* __restrict__ b_hh,
                                                 const float* __restrict__ b_pi,
                                                 const float* __restrict__ b_vf,
                                                 float* __restrict__ out,
                                                 int Btot, int Tsteps) {
    extern __shared__ char smem[];
    float* Hs = reinterpret_cast<float*>(smem + SM_HS);     // [256][36] : Hs[hid][row]
    uint32_t* Au = reinterpret_cast<uint32_t*>(smem + SM_A); // fp16 h plane

    const int t = threadIdx.x;
    const int lane = t & 31;
    const int wid = t >> 5;
    const int gid = lane >> 2;
    const int tig = lane & 3;
    const int b0 = blockIdx.x * 32;
    const int off = blockIdx.x & 15;             // chunk-order stagger
    const int WOFF0 = SM_W0, WOFF1 = SM_W1, WOFF2 = SM_W2;

    // hoisted gate biases for this thread's hidden pairs
    float2 bR[4], bZ[4], bN[4];
#pragma unroll
    for (int b = 0; b < 4; b++) {
        const int hid0 = (4 * wid + b) * 8 + tig * 2;
        bR[b] = *reinterpret_cast<const float2*>(&b_hh[hid0]);
        bZ[b] = *reinterpret_cast<const float2*>(&b_hh[H + hid0]);
        bN[b] = *reinterpret_cast<const float2*>(&b_hh[2 * H + hid0]);
    }

    for (int i = t; i < H * HS_PITCH; i += 256) Hs[i] = 0.f;
    __syncthreads();

    for (int st = 0; st < Tsteps; st++) {
        // issue first two chunk loads (prev step's final sync quiesced all buffers)
        load_wchunk(smem + WOFF0, (off + 0) & 15, t);
        CP_COMMIT;
        load_wchunk(smem + WOFF1, (off + 1) & 15, t);
        CP_COMMIT;

        // A-build: h -> fp16 plane [chunk][k8-half][row][8]
        {
            const int hg = t >> 5;               // hidden group: 32 hids
#pragma unroll
            for (int j = 0; j < 16; j++) {
                const int hid0 = hg * 32 + 2 * j;
                float v0 = Hs[hid0 * HS_PITCH + lane];
                float v1 = Hs[(hid0 + 1) * HS_PITCH + lane];
                __half2 p;
                p.x = __float2half_rn(v0);
                p.y = __float2half_rn(v1);
                const int c = hid0 >> 4, hf = (hid0 >> 3) & 1, e = hid0 & 7;
                const int idx = ((c * 2 + hf) * 32 + lane) * 4 + (e >> 1);
                reinterpret_cast<__half2*>(Au)[idx] = p;
            }
        }

        float acc[2][12][4];
#pragma unroll
        for (int m = 0; m < 2; m++)
#pragma unroll
            for (int nt = 0; nt < 12; nt++)
#pragma unroll
                for (int j = 0; j < 4; j++) acc[m][nt][j] = 0.f;

        for (int c = 0; c < 16; c++) {
            if (c + 2 < 16) { CP_WAIT1; } else { CP_WAIT0; }
            __syncthreads();                     // chunk c resident; A plane visible
            if (c + 2 < 16) {
                const int wb = (c + 2) % 3;
                char* dst = smem + (wb == 0 ? WOFF0 : (wb == 1 ? WOFF1 : WOFF2));
                load_wchunk(dst, (off + c + 2) & 15, t);
                CP_COMMIT;
            }
            const int cc = (off + c) & 15;       // actual chunk index
            const int cb = c % 3;
            const char* Wc = smem + (cb == 0 ? WOFF0 : (cb == 1 ? WOFF1 : WOFF2));
            const uint32_t* Wh = reinterpret_cast<const uint32_t*>(Wc);
            const uint32_t* Wl = reinterpret_cast<const uint32_t*>(Wc + WCHUNK);
            const uint32_t* Ac = Au + cc * 256;

            uint32_t ah[2][4];
#pragma unroll
            for (int m = 0; m < 2; m++) {
                const int base = gid + m * 16;
                ah[m][0] = Ac[base * 4 + tig];
                ah[m][1] = Ac[(base + 8) * 4 + tig];
                ah[m][2] = Ac[128 + base * 4 + tig];
                ah[m][3] = Ac[128 + (base + 8) * 4 + tig];
            }
#pragma unroll
            for (int nt = 0; nt < 12; nt++) {
                const int n = (wid * 12 + nt) * 8 + gid;
                uint32_t bh[2], bl[2];
                bh[0] = Wh[n * 4 + tig];
                bh[1] = Wh[3072 + n * 4 + tig];
                bl[0] = Wl[n * 4 + tig];
                bl[1] = Wl[3072 + n * 4 + tig];
                MMA_F16(acc[0][nt], ah[0], bh);
                MMA_F16(acc[1][nt], ah[1], bh);
                MMA_F16(acc[0][nt], ah[0], bl);
                MMA_F16(acc[1][nt], ah[1], bl);
            }
        }

        // gate epilogue: thread-local r/z/n combine + h update
#pragma unroll
        for (int m = 0; m < 2; m++)
#pragma unroll
            for (int rr = 0; rr < 2; rr++) {
                const int row = gid + m * 16 + rr * 8;
                const size_t gro = ((size_t)(b0 + row) * Tsteps + st) * (size_t)G3;
#pragma unroll
                for (int b = 0; b < 4; b++) {
                    const int hid0 = (4 * wid + b) * 8 + tig * 2;
                    const float2 xr = *reinterpret_cast<const float2*>(&g_xg[gro + hid0]);
                    const float2 xz = *reinterpret_cast<const float2*>(&g_xg[gro + H + hid0]);
                    const float2 xn = *reinterpret_cast<const float2*>(&g_xg[gro + 2 * H + hid0]);
                    const float hr0 = acc[m][b * 3 + 0][rr * 2];
                    const float hr1 = acc[m][b * 3 + 0][rr * 2 + 1];
                    const float hz0 = acc[m][b * 3 + 1][rr * 2];
                    const float hz1 = acc[m][b * 3 + 1][rr * 2 + 1];
                    const float hn0 = acc[m][b * 3 + 2][rr * 2];
                    const float hn1 = acc[m][b * 3 + 2][rr * 2 + 1];
                    {
                        const float r = sigf(xr.x + hr0 + bR[b].x);
                        const float z = sigf(xz.x + hz0 + bZ[b].x);
                        const float n = tanhfast(xn.x + r * (hn0 + bN[b].x));
                        const float hold = Hs[hid0 * HS_PITCH + row];
                        Hs[hid0 * HS_PITCH + row] = (1.f - z) * n + z * hold;
                    }
                    {
                        const float r = sigf(xr.y + hr1 + bR[b].y);
                        const float z = sigf(xz.y + hz1 + bZ[b].y);
                        const float n = tanhfast(xn.y + r * (hn1 + bN[b].y));
                        const float hold = Hs[(hid0 + 1) * HS_PITCH + row];
                        Hs[(hid0 + 1) * HS_PITCH + row] = (1.f - z) * n + z * hold;
                    }
                }
            }
        __syncthreads();                         // Hs complete; all buffers quiesced
    }

    // LeakyReLU on final h
    for (int idx = t; idx < H * 32; idx += 256) {
        const int hid = idx >> 5, row = idx & 31;
        float v = Hs[hid * HS_PITCH + row];
        Hs[hid * HS_PITCH + row] = (v >= 0.f) ? v : 0.01f * v;
    }
    __syncthreads();

    // heads: [32,256] @ [256,128] (fp32 scalar, reuse W buffer region)
    float* Ws0 = reinterpret_cast<float*>(smem);
    float acc2[4][4];
#pragma unroll
    for (int i = 0; i < 4; i++)
#pragma unroll
        for (int j = 0; j < 4; j++) acc2[i][j] = 0.f;

    for (int k0 = 0; k0 < H; k0 += 16) {
#pragma unroll
        for (int q = 0; q < 2; q++) {
            int f4 = t + 256 * q, row = f4 >> 5, c4 = f4 & 31;
            *reinterpret_cast<float4*>(&Ws0[row * HEADN + c4 * 4]) =
                *reinterpret_cast<const float4*>(&g_whead[(size_t)(k0 + row) * HEADN + c4 * 4]);
        }
        __syncthreads();
#pragma unroll
        for (int kk = 0; kk < 16; kk++) {
            float4 av = *reinterpret_cast<const float4*>(&Hs[(k0 + kk) * HS_PITCH + wid * 4]);
            float a[4] = {av.x, av.y, av.z, av.w};
#pragma unroll
            for (int j = 0; j < 4; j++) {
                float wt = Ws0[kk * HEADN + lane + 32 * j];
#pragma unroll
                for (int i = 0; i < 4; i++)
                    acc2[i][j] = fmaf(a[i], wt, acc2[i][j]);
            }
        }
        __syncthreads();
    }

#pragma unroll
    for (int j = 0; j < 4; j++) {
        const int c = lane + 32 * j;
        const float bias = (c < 64) ? b_pi[c] : b_vf[c - 64];
#pragma unroll
        for (int ri = 0; ri < 4; ri++) {
            const int row = wid * 4 + ri;
            float y = acc2[ri][j] + bias;
            y = (y >= 0.f) ? y : 0.01f * y;
            size_t o = (c < 64)
                ? ((size_t)(b0 + row) * 64 + c)
                : ((size_t)Btot * 64 + (size_t)(b0 + row) * 64 + (c - 64));
            out[o] = y;
        }
    }
}

// ---------------- launch ----------------
extern "C" void kernel_launch(void* const* d_in, const int* in_sizes, int n_in,
                              void* d_out, int out_size) {
    const float* feats = (const float*)d_in[0];
    const float* w_ih  = (const float*)d_in[1];
    const float* w_hh  = (const float*)d_in[2];
    const float* b_ih  = (const float*)d_in[3];
    const float* b_hh  = (const float*)d_in[4];
    const float* w_pi  = (const float*)d_in[5];
    const float* b_pi  = (const float*)d_in[6];
    const float* w_vf  = (const float*)d_in[7];
    const float* b_vf  = (const float*)d_in[8];
    float* out = (float*)d_out;

    const int Btot   = out_size / 128;
    const int Tsteps = in_sizes[0] / (Btot * FD);
    const int rows   = Btot * Tsteps;

    const size_t smemX = (size_t)(2 * 128 * XP) * sizeof(uint32_t);   // ~132 KB
    cudaFuncSetAttribute(xgates_mma_sync, cudaFuncAttributeMaxDynamicSharedMemorySize, (int)smemX);
    cudaFuncSetAttribute(gru_recur, cudaFuncAttributeMaxDynamicSharedMemorySize, SM_TOT);

    pack_weights<<<64, 256>>>(w_hh, w_pi, w_vf);
    xgates_mma_sync<<<dim3(rows / 128, G3 / 128), 256, smemX>>>(feats, w_ih, b_ih);
    gru_recur<<<Btot / 32, 256, SM_TOT>>>(b_hh, b_pi, b_vf, out, Btot, Tsteps);
}